// round 17
// baseline (speedup 1.0000x reference)
#include <cuda_runtime.h>

// Problem constants (fixed shapes: B=1, C=1, H=W=96)
#define NN       9216
#define WW       96
#define INV_SXY  (1.0f / 15.0f)
#define SRGB_SCL 8.0f
#define LOG2E    1.4426950408889634f
#define NHL2E    (-0.7213475204444817f)   // -0.5 * log2(e)

// 48x48 grid of 192x192 tiles -> 1176 tile-pairs; each split into 2 blocks
// whose j-range is ONE image row (96 px = 48 pairs) so dy is a per-thread
// constant folded into the i-side bias. IPT=1 / TPB=192: minimal per-thread
// register state -> ~48 resident warps/SM (vs 32 at IPT=3).
#define NB      48
#define TILE    192            // NN / NB
#define NPAIR   (TILE / 2)     // 96 j-pairs per tile
#define JROW    48             // j-pairs per block = one image row
#define TPB     192            // == TILE, one i per thread
#define NTPAIRS (NB * (NB + 1) / 2)   // 1176
#define NBLOCKS (NTPAIRS * 2)         // 2352

// ---- f32x2 helpers (sm_103a packed fp32 pipe; ptxas won't auto-fuse) ----
typedef unsigned long long u64;
__device__ __forceinline__ u64 pack2(float lo, float hi) {
    u64 r; asm("mov.b64 %0, {%1,%2};" : "=l"(r) : "f"(lo), "f"(hi)); return r;
}
__device__ __forceinline__ void unpack2(u64 v, float& lo, float& hi) {
    asm("mov.b64 {%0,%1}, %2;" : "=f"(lo), "=f"(hi) : "l"(v));
}
__device__ __forceinline__ u64 fma2(u64 a, u64 b, u64 c) {
    u64 r; asm("fma.rn.f32x2 %0, %1, %2, %3;" : "=l"(r) : "l"(a), "l"(b), "l"(c)); return r;
}
__device__ __forceinline__ u64 add2(u64 a, u64 b) {
    u64 r; asm("add.rn.f32x2 %0, %1, %2;" : "=l"(r) : "l"(a), "l"(b)); return r;
}
__device__ __forceinline__ float ex2f(float a) {
    float w; asm("ex2.approx.ftz.f32 %0, %1;" : "=f"(w) : "f"(a)); return w;
}

// i-side per pixel: {L2E*fr, L2E*fg, L2E*fb, NHL2E*|frgb|^2}, f = 8*rgb
__device__ float4 g_iA[NN];
__device__ float  g_is[NN];
// j-side pair-packed (pair p = pixels 2p,2p+1); each 16B = two f32x2 operands:
// q0 = {fx0,fx1 | fr0,fr1}   q1 = {fg0,fg1 | fb0,fb1}
// q2 = {bj0,bj1 | p0, p1 }   b = NHL2E*(fx^2+|frgb|^2), p = 1-2s
__device__ float4 g_q0[NN / 2];
__device__ float4 g_q1[NN / 2];
__device__ float4 g_q2[NN / 2];

__global__ void precompute_kernel(const float* __restrict__ inp,
                                  const float* __restrict__ img,
                                  float* __restrict__ out, int out_size) {
    int p = blockIdx.x * blockDim.x + threadIdx.x;
    if (p < out_size) out[p] = 0.0f;           // fused output zeroing
    if (p >= NN / 2) return;
    float fx[2], fr[2], fg[2], fb[2], bj[2], pp[2];
#pragma unroll
    for (int l = 0; l < 2; l++) {
        int n = 2 * p + l;
        float x = (float)(n % WW) * INV_SXY;
        float r = img[n]          * SRGB_SCL;
        float g = img[NN + n]     * SRGB_SCL;
        float b = img[2 * NN + n] * SRGB_SCL;
        float s = inp[n];
        fx[l] = x; fr[l] = r; fg[l] = g; fb[l] = b;
        bj[l] = NHL2E * (x * x + r * r + g * g + b * b);
        pp[l] = fmaf(-2.0f, s, 1.0f);
        g_iA[n] = make_float4(LOG2E * r, LOG2E * g, LOG2E * b,
                              NHL2E * (r * r + g * g + b * b));
        g_is[n] = s;
    }
    g_q0[p] = make_float4(fx[0], fx[1], fr[0], fr[1]);
    g_q1[p] = make_float4(fg[0], fg[1], fb[0], fb[1]);
    g_q2[p] = make_float4(bj[0], bj[1], pp[0], pp[1]);
}

// w_ij = 2^( a_i + b_j + Fx*gx + Fr*gr + Fg*gg + Fb*gb ) = exp(-0.5*d2)
// Dual accumulators (identical loop for diag/off-diag tile-pairs):
//   accW += {w0,w1},  accWP = fma2(W2, P2_raw, accWP)   (P2 straight from smem)
// Epilogue:
//   diag (t=(1+p)/2):  tot += s_i * 0.5*(SumW + SumWP)
//   off  (c=0.5+p*sih): tot += 0.5*SumW + sih_i*SumWP   (covers both orders)
// 2-stage deferral: EX2+acc of jj-1 runs inside iteration jj.
__global__ __launch_bounds__(TPB)
void crf_main_kernel(float* __restrict__ out) {
    __shared__ ulonglong2 sQ0[JROW], sQ1[JROW], sQ2[JROW];
    __shared__ float      sred[TPB / 32];

    // blockIdx -> (tile-pair, j-row); decode pair -> (bi, bj), bi <= bj
    int bp   = blockIdx.x >> 1;
    int half = blockIdx.x & 1;
    int bi = 0;
    while (bp >= NB - bi) { bp -= NB - bi; bi++; }
    int bj = bi + bp;

    const int t  = threadIdx.x;
    const int i0 = bi * TILE;
    const int jp = bj * NPAIR + half * JROW;    // j-pair base (one image row)
    const int yj = 2 * bj + half;               // fixed j row

    const ulonglong2* __restrict__ gq0 = (const ulonglong2*)g_q0;
    const ulonglong2* __restrict__ gq1 = (const ulonglong2*)g_q1;
    const ulonglong2* __restrict__ gq2 = (const ulonglong2*)g_q2;
    if (t < JROW) {
        sQ0[t] = gq0[jp + t];
        sQ1[t] = gq1[jp + t];
        sQ2[t] = gq2[jp + t];
    }

    // per-thread i state (one i per thread; broadcast-packed, loop-invariant)
    u64 FX, FR, FG, FB, A2, accW = 0ull, accWP = 0ull;
    float sih;
    {
        int xi = (t >= WW) ? t - WW : t;
        int yi = 2 * bi + (t >= WW);
        float4 A = g_iA[i0 + t];
        float  s = g_is[i0 + t];
        float fxi = (float)xi * INV_SXY;
        float dy  = (float)(yi - yj) * INV_SXY;
        float a   = A.w + NHL2E * (fxi * fxi + dy * dy);
        FX = pack2(LOG2E * fxi, LOG2E * fxi);
        FR = pack2(A.x, A.x);
        FG = pack2(A.y, A.y);
        FB = pack2(A.z, A.z);
        A2 = pack2(a, a);
        sih = s - 0.5f;
    }
    __syncthreads();

    u64 argP;           // arg(jj-1), awaiting EX2
    u64 P2p;            // p-pair of jj-1 (raw smem u64, consumed by accWP)

#define BUILD_ARG()                                \
    do { u64 arg = add2(A2, B2);                   \
         arg = fma2(FX, Gx, arg);                  \
         arg = fma2(FR, Gr, arg);                  \
         arg = fma2(FG, Gg, arg);                  \
         argP = fma2(FB, Gb, arg); } while (0)

    {   // jj = 0: build only
        ulonglong2 Q0 = sQ0[0], Q1 = sQ1[0], Q2 = sQ2[0];
        u64 Gx = Q0.x, Gr = Q0.y, Gg = Q1.x, Gb = Q1.y, B2 = Q2.x;
        P2p = Q2.y;
        BUILD_ARG();
    }
#pragma unroll 4
    for (int jj = 1; jj < JROW; jj++) {
        ulonglong2 Q0 = sQ0[jj], Q1 = sQ1[jj], Q2 = sQ2[jj];
        u64 Gx = Q0.x, Gr = Q0.y, Gg = Q1.x, Gb = Q1.y, B2 = Q2.x;
        u64 P2c = Q2.y;
        // EX2 of arg(jj-1)
        float a0, a1; unpack2(argP, a0, a1);
        float w0 = ex2f(a0), w1 = ex2f(a1);
        // build arg(jj) (fills the MUFU latency window)
        BUILD_ARG();
        // accumulate (jj-1)
        u64 W2 = pack2(w0, w1);
        accW  = add2(accW, W2);
        accWP = fma2(W2, P2p, accWP);
        P2p = P2c;
    }
    {   // drain last iteration
        float a0, a1; unpack2(argP, a0, a1);
        u64 W2 = pack2(ex2f(a0), ex2f(a1));
        accW  = add2(accW, W2);
        accWP = fma2(W2, P2p, accWP);
    }
#undef BUILD_ARG

    float aw0, aw1, ap0, ap1;
    unpack2(accW,  aw0, aw1);
    unpack2(accWP, ap0, ap1);
    float tot;
    if (bi == bj) {
        tot = (sih + 0.5f) * 0.5f * (aw0 + aw1 + ap0 + ap1);
    } else {
        tot = 0.5f * (aw0 + aw1) + sih * (ap0 + ap1);
    }
    tot *= (1.0f / (float)NN);

    // Block reduce: warp shuffle then smem (TPB = 192 -> 6 warps)
#pragma unroll
    for (int off = 16; off > 0; off >>= 1)
        tot += __shfl_xor_sync(0xFFFFFFFFu, tot, off);
    if ((t & 31) == 0) sred[t >> 5] = tot;
    __syncthreads();
    if (t == 0) {
        float v = 0.0f;
#pragma unroll
        for (int k = 0; k < TPB / 32; k++) v += sred[k];
        atomicAdd(out, v);
    }
}

extern "C" void kernel_launch(void* const* d_in, const int* in_sizes, int n_in,
                              void* d_out, int out_size) {
    const float* inp = (const float*)d_in[0];   // [1,1,96,96] seg probs
    const float* img = (const float*)d_in[1];   // [1,3,96,96] rgb
    float* out = (float*)d_out;

    precompute_kernel<<<(NN / 2 + 255) / 256, 256>>>(inp, img, out, out_size);
    crf_main_kernel<<<NBLOCKS, TPB>>>(out);
}